// round 2
// baseline (speedup 1.0000x reference)
#include <cuda_runtime.h>
#include <cuda_bf16.h>
#include <cstdint>

// ConvTranspose2d (kernel==stride==2) as GEMM:
//   M = 8*64*64 = 32768 pixels p=(b,h,w), N = 256*2*2 = 1024 (o,i,j), K = 512 (c)
//   A[p][c] = x[b,c,h,w]   (x is [8][512][64][64], p-contiguous per channel plane)
//   B[c][n] = weight[c][o][i][j]  (weight is [512][256][2][2], n-contiguous)
//   out[b][o][2h+i][2w+j] = C[p][n] + bias[o]
// fp32 accuracy via 3-term bf16 split: a*b ~= ah*bh + ah*bl + al*bh

#define BM 128
#define BN 128
#define BK 32
#define KSTR 40   // padded row stride in bf16 elems (80 bytes) -> conflict-free frags

__global__ __launch_bounds__(256)
void convt_gemm_bf16split(const float* __restrict__ x,
                          const float* __restrict__ w,
                          const float* __restrict__ bias,
                          float* __restrict__ out)
{
    __shared__ __nv_bfloat16 AsH[BM * KSTR];
    __shared__ __nv_bfloat16 AsL[BM * KSTR];
    __shared__ __nv_bfloat16 BsH[BN * KSTR];
    __shared__ __nv_bfloat16 BsL[BN * KSTR];

    const int tid  = threadIdx.x;
    const int lane = tid & 31;
    const int warp = tid >> 5;
    const int g    = lane >> 2;   // groupID (row within mma fragment)
    const int tg   = lane & 3;    // thread-in-group (k/col pair selector)
    const int wm   = warp & 3;    // warp row   (4 x 32 = 128 M)
    const int wn   = warp >> 2;   // warp col   (2 x 64 = 128 N)

    const int mb = blockIdx.y;    // 0..255  (M tile)
    const int nb = blockIdx.x;    // 0..7    (N tile)

    const int bidx = mb >> 5;                 // batch (32 M-tiles per batch plane)
    const int pin  = (mb & 31) * BM;          // pixel offset inside batch plane
    const float* xb = x + (size_t)bidx * 512 * 4096;

    float acc[2][8][4];
    #pragma unroll
    for (int i = 0; i < 2; i++)
        #pragma unroll
        for (int j = 0; j < 8; j++)
            #pragma unroll
            for (int r = 0; r < 4; r++) acc[i][j][r] = 0.f;

    for (int k0 = 0; k0 < 512; k0 += BK) {
        // ---- stage A: 128 pixels x 32 channels, split to hi/lo bf16 ----
        #pragma unroll
        for (int it = 0; it < (BM * BK) / 256; it++) {   // 16 iters
            int e = tid + it * 256;
            int c = e >> 7;        // 0..31
            int p = e & 127;       // 0..127 (coalesced along pixels)
            float v = xb[(size_t)(k0 + c) * 4096 + pin + p];
            __nv_bfloat16 hi = __float2bfloat16(v);
            __nv_bfloat16 lo = __float2bfloat16(v - __bfloat162float(hi));
            AsH[p * KSTR + c] = hi;
            AsL[p * KSTR + c] = lo;
        }
        // ---- stage B: 32 k x 128 n (w is [512][1024] row-major), transpose to [n][k] ----
        #pragma unroll
        for (int it = 0; it < (BK * BN) / 256; it++) {   // 16 iters
            int e = tid + it * 256;
            int k = e >> 7;        // 0..31
            int n = e & 127;       // coalesced along n
            float v = w[(size_t)(k0 + k) * 1024 + nb * 128 + n];
            __nv_bfloat16 hi = __float2bfloat16(v);
            __nv_bfloat16 lo = __float2bfloat16(v - __bfloat162float(hi));
            BsH[n * KSTR + k] = hi;
            BsL[n * KSTR + k] = lo;
        }
        __syncthreads();

        #pragma unroll
        for (int pass = 0; pass < 3; pass++) {
            const __nv_bfloat16* Ab = (pass == 2) ? AsL : AsH;
            const __nv_bfloat16* Bb = (pass == 1) ? BsL : BsH;
            #pragma unroll
            for (int kk = 0; kk < BK; kk += 16) {
                uint32_t a[2][4], b[8][2];
                #pragma unroll
                for (int mt = 0; mt < 2; mt++) {
                    int rb = wm * 32 + mt * 16;
                    const __nv_bfloat16* ap = Ab + (rb + g) * KSTR + kk + tg * 2;
                    a[mt][0] = *(const uint32_t*)(ap);
                    a[mt][1] = *(const uint32_t*)(ap + 8 * KSTR);
                    a[mt][2] = *(const uint32_t*)(ap + 8);
                    a[mt][3] = *(const uint32_t*)(ap + 8 * KSTR + 8);
                }
                #pragma unroll
                for (int nt = 0; nt < 8; nt++) {
                    const __nv_bfloat16* bp = Bb + (wn * 64 + nt * 8 + g) * KSTR + kk + tg * 2;
                    b[nt][0] = *(const uint32_t*)(bp);
                    b[nt][1] = *(const uint32_t*)(bp + 8);
                }
                #pragma unroll
                for (int mt = 0; mt < 2; mt++)
                    #pragma unroll
                    for (int nt = 0; nt < 8; nt++) {
                        asm volatile(
                            "mma.sync.aligned.m16n8k16.row.col.f32.bf16.bf16.f32 "
                            "{%0,%1,%2,%3}, {%4,%5,%6,%7}, {%8,%9}, {%0,%1,%2,%3};\n"
                            : "+f"(acc[mt][nt][0]), "+f"(acc[mt][nt][1]),
                              "+f"(acc[mt][nt][2]), "+f"(acc[mt][nt][3])
                            : "r"(a[mt][0]), "r"(a[mt][1]), "r"(a[mt][2]), "r"(a[mt][3]),
                              "r"(b[nt][0]), "r"(b[nt][1]));
                    }
            }
        }
        __syncthreads();
    }

    // ---- epilogue: scatter to out[b][o][2h+i][2w+j], fused bias, float2 stores ----
    #pragma unroll
    for (int mt = 0; mt < 2; mt++) {
        int r0 = mb * 128 + wm * 32 + mt * 16 + g;
        #pragma unroll
        for (int half = 0; half < 2; half++) {
            int p  = r0 + half * 8;
            int bb = p >> 12;
            int hw = p & 4095;
            int h  = hw >> 6;
            int wp = hw & 63;
            #pragma unroll
            for (int nt = 0; nt < 8; nt++) {
                int n  = nb * 128 + wn * 64 + nt * 8 + tg * 2;   // even -> j = 0,1 pair
                int o  = n >> 2;
                int ii = (n >> 1) & 1;
                float bo = __ldg(bias + o);
                size_t addr = (((size_t)(bb * 256 + o) * 128) + (h * 2 + ii)) * 128 + wp * 2;
                float2 v;
                v.x = acc[mt][nt][half * 2 + 0] + bo;
                v.y = acc[mt][nt][half * 2 + 1] + bo;
                *(float2*)(out + addr) = v;
            }
        }
    }
}

extern "C" void kernel_launch(void* const* d_in, const int* in_sizes, int n_in,
                              void* d_out, int out_size)
{
    const float* x    = (const float*)d_in[0];   // [8,512,64,64]
    const float* wgt  = (const float*)d_in[1];   // [512,256,2,2]
    const float* bias = (const float*)d_in[2];   // [256]
    float* out = (float*)d_out;                  // [8,256,128,128]

    dim3 grid(1024 / BN, 32768 / BM);            // (8, 256) — N fastest for A-tile L2 reuse
    convt_gemm_bf16split<<<grid, 256>>>(x, wgt, bias, out);
}

// round 4
// speedup vs baseline: 2.0238x; 2.0238x over previous
#include <cuda_runtime.h>
#include <cuda_bf16.h>
#include <cstdint>

// ConvTranspose2d (k==s==2) == GEMM: M=32768 pixels, N=1024 (o*4+i*2+j), K=512 (c)
// fp32 accuracy via 3-term bf16 split: a*b ~= aH*bH + aH*bL + aL*bH
// Phase 1: transpose+split  x -> g_xH/g_xL [32768][512],  w -> g_wH/g_wL [1024][512]
// Phase 2: mma.sync bf16 GEMM (sm_103 fallback HMMA; tcgen05 is compute_103a-gated
//          and this toolchain targets compute_103), cp.async double-buffered,
//          ldmatrix fragment loads, fused bias + pixel-shuffle epilogue.

#define M_TOTAL 32768
#define K_TOTAL 512
#define N_TOTAL 1024
#define BM 128
#define BN 128
#define BK 32
#define KITERS (K_TOTAL / BK)
#define STAGE_BYTES 32768            // A: 128 rows * 128B  +  B: 128 rows * 128B
#define SMEM_TOTAL (2 * STAGE_BYTES) // 64 KB double-buffered

// -------- device scratch (allocation-free rule: __device__ globals) --------
__device__ __nv_bfloat16 g_xH[(size_t)M_TOTAL * K_TOTAL];
__device__ __nv_bfloat16 g_xL[(size_t)M_TOTAL * K_TOTAL];
__device__ __nv_bfloat16 g_wH[(size_t)N_TOTAL * K_TOTAL];
__device__ __nv_bfloat16 g_wL[(size_t)N_TOTAL * K_TOTAL];

// ---------------- helpers ----------------
__device__ __forceinline__ uint32_t smem_u32(const void* p) {
    uint32_t a;
    asm("{ .reg .u64 t; cvta.to.shared.u64 t, %1; cvt.u32.u64 %0, t; }" : "=r"(a) : "l"(p));
    return a;
}

#define CP_ASYNC16(dst, src) \
    asm volatile("cp.async.cg.shared.global [%0], [%1], 16;" :: "r"(dst), "l"(src) : "memory")
#define CP_COMMIT()  asm volatile("cp.async.commit_group;" ::: "memory")
#define CP_WAIT1()   asm volatile("cp.async.wait_group 1;" ::: "memory")
#define CP_WAIT0()   asm volatile("cp.async.wait_group 0;" ::: "memory")

#define LDMX4(R, addr)                                                          \
    asm volatile("ldmatrix.sync.aligned.m8n8.x4.shared.b16 {%0,%1,%2,%3}, [%4];"\
        : "=r"((R)[0]), "=r"((R)[1]), "=r"((R)[2]), "=r"((R)[3]) : "r"(addr))
#define LDMX2(R, addr)                                                          \
    asm volatile("ldmatrix.sync.aligned.m8n8.x2.shared.b16 {%0,%1}, [%2];"      \
        : "=r"((R)[0]), "=r"((R)[1]) : "r"(addr))

#define MMA16816(ACC, A, B)                                                     \
    asm volatile("mma.sync.aligned.m16n8k16.row.col.f32.bf16.bf16.f32 "         \
        "{%0,%1,%2,%3}, {%4,%5,%6,%7}, {%8,%9}, {%0,%1,%2,%3};"                 \
        : "+f"((ACC)[0]), "+f"((ACC)[1]), "+f"((ACC)[2]), "+f"((ACC)[3])        \
        : "r"((A)[0]), "r"((A)[1]), "r"((A)[2]), "r"((A)[3]),                   \
          "r"((B)[0]), "r"((B)[1]))

// ---------------- Phase 1: transpose + bf16 split ----------------
// src: [R][C] fp32 (per batch in z) -> dstH/dstL: [C][R] bf16
__global__ void tsplit_kernel(const float* __restrict__ src,
                              __nv_bfloat16* __restrict__ dH,
                              __nv_bfloat16* __restrict__ dL,
                              int R, int C)
{
    __shared__ float tile[32][33];
    int b = blockIdx.z;
    src += (size_t)b * R * C;
    dH  += (size_t)b * R * C;
    dL  += (size_t)b * R * C;
    int p0 = blockIdx.x * 32;
    int c0 = blockIdx.y * 32;
    int tx = threadIdx.x, ty = threadIdx.y;
    #pragma unroll
    for (int i = 0; i < 32; i += 8)
        tile[ty + i][tx] = src[(size_t)(c0 + ty + i) * C + p0 + tx];
    __syncthreads();
    #pragma unroll
    for (int i = 0; i < 32; i += 8) {
        float v = tile[tx][ty + i];
        __nv_bfloat16 hi = __float2bfloat16(v);
        __nv_bfloat16 lo = __float2bfloat16(v - __bfloat162float(hi));
        size_t idx = (size_t)(p0 + ty + i) * R + c0 + tx;
        dH[idx] = hi;
        dL[idx] = lo;
    }
}

// ---------------- Phase 2: mma.sync GEMM ----------------
// SMEM tile layout (per stage): 128 rows x 128 bytes. Row = [H: 32 bf16 | L: 32 bf16],
// 16B chunk c stored at ((c ^ (row&7)) * 16). Conflict-free for cp.async stores and
// all ldmatrix 8-lane phases.

__global__ __launch_bounds__(256)
void gemm_mma_kernel(const float* __restrict__ bias, float* __restrict__ out)
{
    extern __shared__ char smem[];
    const uint32_t sbase = smem_u32(smem);

    const int tid  = threadIdx.x;
    const int lane = tid & 31;
    const int warp = tid >> 5;
    const int g    = lane >> 2;   // mma row within fragment
    const int tg   = lane & 3;    // mma col-pair selector
    const int wm   = warp & 3;    // 4 warps along M (32 each)
    const int wn   = warp >> 2;   // 2 warps along N (64 each)

    const int nb = blockIdx.x;    // 0..7   (N tile of 128)
    const int mb = blockIdx.y;    // 0..255 (M tile of 128)

    const __nv_bfloat16* gAH = g_xH + (size_t)mb * BM * K_TOTAL;
    const __nv_bfloat16* gAL = g_xL + (size_t)mb * BM * K_TOTAL;
    const __nv_bfloat16* gBH = g_wH + (size_t)nb * BN * K_TOTAL;
    const __nv_bfloat16* gBL = g_wL + (size_t)nb * BN * K_TOTAL;

    // ldmatrix per-lane addressing precompute
    const int rA   = (lane & 7) + ((lane >> 3) & 1) * 8;  // row-in-16 for A x4
    const int selA = lane >> 4;                            // k8-chunk select for A x4
    const int xorA = lane & 7;
    const uint32_t aBase = (uint32_t)(wm * 32 + rA) * 128;
    const int rB   = lane & 7;                             // row for B x2 (lanes 0..15 used)
    const int selB = (lane >> 3) & 1;
    const uint32_t bBase = (uint32_t)(wn * 64 + rB) * 128;

    float acc[2][8][4];
    #pragma unroll
    for (int i = 0; i < 2; i++)
        #pragma unroll
        for (int j = 0; j < 8; j++)
            #pragma unroll
            for (int r = 0; r < 4; r++) acc[i][j][r] = 0.f;

    // ---- async staging of one k-stage into buffer buf ----
    auto stage_load = [&](int it, int buf) {
        const int k0 = it * BK;
        const uint32_t sA = sbase + buf * STAGE_BYTES;
        const uint32_t sB = sA + 16384;
        #pragma unroll
        for (int i = 0; i < 4; i++) {                 // A: 1024 chunks of 16B
            int q = tid + i * 256;
            int r = q >> 3, c = q & 7;
            const __nv_bfloat16* src = (c < 4)
                ? gAH + (size_t)r * K_TOTAL + k0 + c * 8
                : gAL + (size_t)r * K_TOTAL + k0 + (c - 4) * 8;
            CP_ASYNC16(sA + (uint32_t)r * 128 + ((c ^ (r & 7)) << 4), src);
        }
        #pragma unroll
        for (int i = 0; i < 4; i++) {                 // B: 1024 chunks of 16B
            int q = tid + i * 256;
            int r = q >> 3, c = q & 7;
            const __nv_bfloat16* src = (c < 4)
                ? gBH + (size_t)r * K_TOTAL + k0 + c * 8
                : gBL + (size_t)r * K_TOTAL + k0 + (c - 4) * 8;
            CP_ASYNC16(sB + (uint32_t)r * 128 + ((c ^ (r & 7)) << 4), src);
        }
    };

    stage_load(0, 0);
    CP_COMMIT();

    for (int it = 0; it < KITERS; it++) {
        const int cur = it & 1;
        if (it + 1 < KITERS) {
            stage_load(it + 1, cur ^ 1);
            CP_COMMIT();
            CP_WAIT1();
        } else {
            CP_WAIT0();
        }
        __syncthreads();

        const uint32_t sA = sbase + cur * STAGE_BYTES;
        const uint32_t sB = sA + 16384;

        #pragma unroll
        for (int kc = 0; kc < 2; kc++) {              // two k16 chunks in BK=32
            uint32_t aH[8], aL[8];
            #pragma unroll
            for (int mt = 0; mt < 2; mt++) {
                LDMX4(aH + mt * 4,
                      sA + aBase + mt * 2048 + (uint32_t)(((kc * 2 + selA)     ^ xorA) << 4));
                LDMX4(aL + mt * 4,
                      sA + aBase + mt * 2048 + (uint32_t)(((kc * 2 + selA + 4) ^ xorA) << 4));
            }
            #pragma unroll
            for (int nt = 0; nt < 8; nt++) {
                uint32_t bH[2], bL[2];
                const uint32_t bd = sB + bBase + (uint32_t)nt * 1024;
                LDMX2(bH, bd + (uint32_t)(((kc * 2 + selB)     ^ rB) << 4));
                LDMX2(bL, bd + (uint32_t)(((kc * 2 + selB + 4) ^ rB) << 4));
                MMA16816(acc[0][nt], aH + 0, bH);     // H*H
                MMA16816(acc[1][nt], aH + 4, bH);
                MMA16816(acc[0][nt], aH + 0, bL);     // H*L
                MMA16816(acc[1][nt], aH + 4, bL);
                MMA16816(acc[0][nt], aL + 0, bH);     // L*H
                MMA16816(acc[1][nt], aL + 4, bH);
            }
        }
        __syncthreads();
    }

    // ---- epilogue: scatter to out[b][o][2h+i][2w+j], fused bias, float2 stores ----
    #pragma unroll
    for (int mt = 0; mt < 2; mt++) {
        int r0 = mb * 128 + wm * 32 + mt * 16 + g;
        #pragma unroll
        for (int half = 0; half < 2; half++) {
            int p  = r0 + half * 8;
            int bb = p >> 12;
            int h  = (p >> 6) & 63;
            int wp = p & 63;
            #pragma unroll
            for (int nt = 0; nt < 8; nt++) {
                int n  = nb * 128 + wn * 64 + nt * 8 + tg * 2;   // even -> (j=0, j=1) pair
                int o  = n >> 2;
                int ii = (n >> 1) & 1;
                float bo = __ldg(bias + o);
                size_t addr = (((size_t)(bb * 256 + o) * 128) + (h * 2 + ii)) * 128 + wp * 2;
                float2 v;
                v.x = acc[mt][nt][half * 2 + 0] + bo;
                v.y = acc[mt][nt][half * 2 + 1] + bo;
                *(float2*)(out + addr) = v;
            }
        }
    }
}

// ---------------- launch ----------------
extern "C" void kernel_launch(void* const* d_in, const int* in_sizes, int n_in,
                              void* d_out, int out_size)
{
    const float* x    = (const float*)d_in[0];   // [8,512,64,64]
    const float* wgt  = (const float*)d_in[1];   // [512,256,2,2] -> [512][1024]
    const float* bias = (const float*)d_in[2];   // [256]
    float* out = (float*)d_out;                  // [8,256,128,128]

    void *pxH, *pxL, *pwH, *pwL;
    cudaGetSymbolAddress(&pxH, g_xH);
    cudaGetSymbolAddress(&pxL, g_xL);
    cudaGetSymbolAddress(&pwH, g_wH);
    cudaGetSymbolAddress(&pwL, g_wL);

    // Phase 1: x [512][4096] per batch -> [4096][512]; w [512][1024] -> [1024][512]
    tsplit_kernel<<<dim3(4096 / 32, 512 / 32, 8), dim3(32, 8)>>>(
        x, (__nv_bfloat16*)pxH, (__nv_bfloat16*)pxL, 512, 4096);
    tsplit_kernel<<<dim3(1024 / 32, 512 / 32, 1), dim3(32, 8)>>>(
        wgt, (__nv_bfloat16*)pwH, (__nv_bfloat16*)pwL, 512, 1024);

    // Phase 2
    static int attr_set = 0;
    if (!attr_set) {
        cudaFuncSetAttribute(gemm_mma_kernel,
                             cudaFuncAttributeMaxDynamicSharedMemorySize, SMEM_TOTAL);
        attr_set = 1;
    }
    dim3 grid(N_TOTAL / BN, M_TOTAL / BM);   // (8, 256) — nb fastest for A-tile L2 reuse
    gemm_mma_kernel<<<grid, 256, SMEM_TOTAL>>>(bias, out);
}

// round 5
// speedup vs baseline: 2.0813x; 1.0284x over previous
#include <cuda_runtime.h>
#include <cuda_bf16.h>
#include <cstdint>

// ConvTranspose2d (k==s==2) == GEMM: M=32768 pixels, N=1024 (o*4+i*2+j), K=512 (c)
// fp32 accuracy via 3-term bf16 split: a*b ~= aH*bH + aH*bL + aL*bH
// Phase 1: transpose+split  x -> g_xH/g_xL [32768][512],  w -> g_wH/g_wL [1024][512]
// Phase 2: mma.sync bf16 GEMM (tcgen05 is compute_103a-gated; toolchain targets
//          compute_103). 512 threads, 16 warps (4x4), warp tile 32x32, BK=64,
//          double-buffered cp.async, all-LDMX4 fragment loads, fused epilogue.

#define M_TOTAL 32768
#define K_TOTAL 512
#define N_TOTAL 1024
#define BM 128
#define BN 128
#define BK 64
#define KITERS (K_TOTAL / BK)
#define ROWB 256                       // bytes per smem row: H 128 | L 128
#define STAGE_BYTES (2 * 128 * ROWB)   // A 32KB + B 32KB
#define SMEM_TOTAL (2 * STAGE_BYTES)   // 128KB double-buffered

// -------- device scratch (allocation-free rule: __device__ globals) --------
__device__ __nv_bfloat16 g_xH[(size_t)M_TOTAL * K_TOTAL];
__device__ __nv_bfloat16 g_xL[(size_t)M_TOTAL * K_TOTAL];
__device__ __nv_bfloat16 g_wH[(size_t)N_TOTAL * K_TOTAL];
__device__ __nv_bfloat16 g_wL[(size_t)N_TOTAL * K_TOTAL];

// ---------------- helpers ----------------
__device__ __forceinline__ uint32_t smem_u32(const void* p) {
    uint32_t a;
    asm("{ .reg .u64 t; cvta.to.shared.u64 t, %1; cvt.u32.u64 %0, t; }" : "=r"(a) : "l"(p));
    return a;
}

#define CP_ASYNC16(dst, src) \
    asm volatile("cp.async.cg.shared.global [%0], [%1], 16;" :: "r"(dst), "l"(src) : "memory")
#define CP_COMMIT()  asm volatile("cp.async.commit_group;" ::: "memory")
#define CP_WAIT1()   asm volatile("cp.async.wait_group 1;" ::: "memory")
#define CP_WAIT0()   asm volatile("cp.async.wait_group 0;" ::: "memory")

#define LDMX4(R, addr)                                                          \
    asm volatile("ldmatrix.sync.aligned.m8n8.x4.shared.b16 {%0,%1,%2,%3}, [%4];"\
        : "=r"((R)[0]), "=r"((R)[1]), "=r"((R)[2]), "=r"((R)[3]) : "r"(addr))

#define MMA16816(ACC, A, B)                                                     \
    asm volatile("mma.sync.aligned.m16n8k16.row.col.f32.bf16.bf16.f32 "         \
        "{%0,%1,%2,%3}, {%4,%5,%6,%7}, {%8,%9}, {%0,%1,%2,%3};"                 \
        : "+f"((ACC)[0]), "+f"((ACC)[1]), "+f"((ACC)[2]), "+f"((ACC)[3])        \
        : "r"((A)[0]), "r"((A)[1]), "r"((A)[2]), "r"((A)[3]),                   \
          "r"((B)[0]), "r"((B)[1]))

// ---------------- Phase 1: transpose + bf16 split ----------------
__global__ void tsplit_kernel(const float* __restrict__ src,
                              __nv_bfloat16* __restrict__ dH,
                              __nv_bfloat16* __restrict__ dL,
                              int R, int C)
{
    __shared__ float tile[32][33];
    int b = blockIdx.z;
    src += (size_t)b * R * C;
    dH  += (size_t)b * R * C;
    dL  += (size_t)b * R * C;
    int p0 = blockIdx.x * 32;
    int c0 = blockIdx.y * 32;
    int tx = threadIdx.x, ty = threadIdx.y;
    #pragma unroll
    for (int i = 0; i < 32; i += 8)
        tile[ty + i][tx] = src[(size_t)(c0 + ty + i) * C + p0 + tx];
    __syncthreads();
    #pragma unroll
    for (int i = 0; i < 32; i += 8) {
        float v = tile[tx][ty + i];
        __nv_bfloat16 hi = __float2bfloat16(v);
        __nv_bfloat16 lo = __float2bfloat16(v - __bfloat162float(hi));
        size_t idx = (size_t)(p0 + ty + i) * R + c0 + tx;
        dH[idx] = hi;
        dL[idx] = lo;
    }
}

// ---------------- Phase 2: mma.sync GEMM ----------------
// SMEM stage: A = 128 rows x 256B, B = 128 rows x 256B.
// Row r: bytes [0,128) = H k-chunks c=0..7 at ((c ^ (r&7))<<4),
//        bytes [128,256) = L chunks, same swizzle.

__global__ __launch_bounds__(512)
void gemm_mma_kernel(const float* __restrict__ bias, float* __restrict__ out)
{
    extern __shared__ char smem[];
    const uint32_t sbase = smem_u32(smem);

    const int tid  = threadIdx.x;
    const int lane = tid & 31;
    const int warp = tid >> 5;
    const int g    = lane >> 2;       // mma row within fragment
    const int tg   = lane & 3;        // mma col-pair selector
    const int wm   = warp & 3;        // 4 warps along M (32 rows each)
    const int wn   = warp >> 2;       // 4 warps along N (32 cols each)

    const int nb = blockIdx.x;        // 0..7   (N tile of 128)
    const int mb = blockIdx.y;        // 0..255 (M tile of 128)

    const __nv_bfloat16* gAH = g_xH + (size_t)mb * BM * K_TOTAL;
    const __nv_bfloat16* gAL = g_xL + (size_t)mb * BM * K_TOTAL;
    const __nv_bfloat16* gBH = g_wH + (size_t)nb * BN * K_TOTAL;
    const __nv_bfloat16* gBL = g_wL + (size_t)nb * BN * K_TOTAL;

    // ldmatrix per-lane addressing
    const int x7   = lane & 7;
    const int rA   = x7 + ((lane >> 3) & 1) * 8;          // row-in-16, A x4
    const int selA = lane >> 4;                           // k8 select, A x4
    const int rB   = ((lane >> 4) << 3) + x7;             // row-in-16, B x4 (nt pair)
    const int selB = (lane >> 3) & 1;                     // k8 select, B x4
    const uint32_t aBase = (uint32_t)(wm * 32 + rA) * ROWB;
    const uint32_t bBase = (uint32_t)(wn * 32 + rB) * ROWB;

    float acc[2][4][4];
    #pragma unroll
    for (int i = 0; i < 2; i++)
        #pragma unroll
        for (int j = 0; j < 4; j++)
            #pragma unroll
            for (int r = 0; r < 4; r++) acc[i][j][r] = 0.f;

    // ---- async staging of one k-stage (BK=64) into buffer buf ----
    auto stage_load = [&](int it, int buf) {
        const int k0 = it * BK;
        const uint32_t sA = sbase + buf * STAGE_BYTES;
        const uint32_t sB = sA + 128 * ROWB;
        #pragma unroll
        for (int i = 0; i < 4; i++) {                 // A: 2048 x 16B chunks
            int q = tid + i * 512;
            int r = q >> 4, c = q & 15;
            const __nv_bfloat16* src = (c < 8)
                ? gAH + (size_t)r * K_TOTAL + k0 + c * 8
                : gAL + (size_t)r * K_TOTAL + k0 + (c - 8) * 8;
            uint32_t off = (c < 8) ? (uint32_t)((c ^ (r & 7)) << 4)
                                   : 128u + (uint32_t)(((c - 8) ^ (r & 7)) << 4);
            CP_ASYNC16(sA + (uint32_t)r * ROWB + off, src);
        }
        #pragma unroll
        for (int i = 0; i < 4; i++) {                 // B: 2048 x 16B chunks
            int q = tid + i * 512;
            int r = q >> 4, c = q & 15;
            const __nv_bfloat16* src = (c < 8)
                ? gBH + (size_t)r * K_TOTAL + k0 + c * 8
                : gBL + (size_t)r * K_TOTAL + k0 + (c - 8) * 8;
            uint32_t off = (c < 8) ? (uint32_t)((c ^ (r & 7)) << 4)
                                   : 128u + (uint32_t)(((c - 8) ^ (r & 7)) << 4);
            CP_ASYNC16(sB + (uint32_t)r * ROWB + off, src);
        }
    };

    stage_load(0, 0);
    CP_COMMIT();

    for (int it = 0; it < KITERS; it++) {
        const int cur = it & 1;
        if (it + 1 < KITERS) {
            stage_load(it + 1, cur ^ 1);
            CP_COMMIT();
            CP_WAIT1();
        } else {
            CP_WAIT0();
        }
        __syncthreads();

        const uint32_t sA = sbase + cur * STAGE_BYTES;
        const uint32_t sB = sA + 128 * ROWB;

        #pragma unroll
        for (int kc = 0; kc < 4; kc++) {              // four k16 chunks in BK=64
            uint32_t aH[8], aL[8], bH[8], bL[8];
            #pragma unroll
            for (int mt = 0; mt < 2; mt++) {
                uint32_t base = sA + aBase + (uint32_t)mt * 16 * ROWB;
                LDMX4(aH + mt * 4, base +        (uint32_t)(((kc * 2 + selA) ^ x7) << 4));
                LDMX4(aL + mt * 4, base + 128u + (uint32_t)(((kc * 2 + selA) ^ x7) << 4));
            }
            #pragma unroll
            for (int ntp = 0; ntp < 2; ntp++) {       // each LDMX4 covers 2 nt
                uint32_t base = sB + bBase + (uint32_t)ntp * 16 * ROWB;
                LDMX4(bH + ntp * 4, base +        (uint32_t)(((kc * 2 + selB) ^ x7) << 4));
                LDMX4(bL + ntp * 4, base + 128u + (uint32_t)(((kc * 2 + selB) ^ x7) << 4));
            }
            #pragma unroll
            for (int mt = 0; mt < 2; mt++)
                #pragma unroll
                for (int nt = 0; nt < 4; nt++) {
                    MMA16816(acc[mt][nt], aH + mt * 4, bH + nt * 2);   // H*H
                    MMA16816(acc[mt][nt], aH + mt * 4, bL + nt * 2);   // H*L
                    MMA16816(acc[mt][nt], aL + mt * 4, bH + nt * 2);   // L*H
                }
        }
        __syncthreads();
    }

    // ---- epilogue: scatter to out[b][o][2h+i][2w+j], fused bias, float2 stores ----
    #pragma unroll
    for (int mt = 0; mt < 2; mt++) {
        int r0 = mb * 128 + wm * 32 + mt * 16 + g;
        #pragma unroll
        for (int half = 0; half < 2; half++) {
            int p  = r0 + half * 8;
            int bb = p >> 12;
            int h  = (p >> 6) & 63;
            int wp = p & 63;
            #pragma unroll
            for (int nt = 0; nt < 4; nt++) {
                int n  = nb * 128 + wn * 32 + nt * 8 + tg * 2;   // even -> (j=0, j=1)
                int o  = n >> 2;
                int ii = (n >> 1) & 1;
                float bo = __ldg(bias + o);
                size_t addr = (((size_t)(bb * 256 + o) * 128) + (h * 2 + ii)) * 128 + wp * 2;
                float2 v;
                v.x = acc[mt][nt][half * 2 + 0] + bo;
                v.y = acc[mt][nt][half * 2 + 1] + bo;
                *(float2*)(out + addr) = v;
            }
        }
    }
}

// ---------------- launch ----------------
extern "C" void kernel_launch(void* const* d_in, const int* in_sizes, int n_in,
                              void* d_out, int out_size)
{
    const float* x    = (const float*)d_in[0];   // [8,512,64,64]
    const float* wgt  = (const float*)d_in[1];   // [512,256,2,2] -> [512][1024]
    const float* bias = (const float*)d_in[2];   // [256]
    float* out = (float*)d_out;                  // [8,256,128,128]

    void *pxH, *pxL, *pwH, *pwL;
    cudaGetSymbolAddress(&pxH, g_xH);
    cudaGetSymbolAddress(&pxL, g_xL);
    cudaGetSymbolAddress(&pwH, g_wH);
    cudaGetSymbolAddress(&pwL, g_wL);

    tsplit_kernel<<<dim3(4096 / 32, 512 / 32, 8), dim3(32, 8)>>>(
        x, (__nv_bfloat16*)pxH, (__nv_bfloat16*)pxL, 512, 4096);
    tsplit_kernel<<<dim3(1024 / 32, 512 / 32, 1), dim3(32, 8)>>>(
        wgt, (__nv_bfloat16*)pwH, (__nv_bfloat16*)pwL, 512, 1024);

    static int attr_set = 0;
    if (!attr_set) {
        cudaFuncSetAttribute(gemm_mma_kernel,
                             cudaFuncAttributeMaxDynamicSharedMemorySize, SMEM_TOTAL);
        attr_set = 1;
    }
    dim3 grid(N_TOTAL / BN, M_TOTAL / BM);   // (8, 256) — nb fastest for A-tile L2 reuse
    gemm_mma_kernel<<<grid, 512, SMEM_TOTAL>>>(bias, out);
}

// round 6
// speedup vs baseline: 4.1233x; 1.9811x over previous
#include <cuda_runtime.h>
#include <cuda_fp16.h>
#include <cstdint>

// ConvTranspose2d (k==s==2) == GEMM: M=32768 pixels, N=1024 (o*4+i*2+j), K=512 (c)
// Single-pass fp16 mma (fp32 accumulate): per-term rounding 2^-11, K=512 random-sum
// -> global rel_err ~2.4e-4 < 1e-3 gate.
// Phase 1: transpose+convert  x -> g_xF [32768][512] fp16,  w -> g_wF [1024][512] fp16
// Phase 2: mma.sync fp16 GEMM (tcgen05 is compute_103a-gated; toolchain targets
//          compute_103). 512 threads, 16 warps (4x4), warp tile 32x32, BK=64,
//          double-buffered cp.async, all-LDMX4 fragment loads, fused epilogue.

#define M_TOTAL 32768
#define K_TOTAL 512
#define N_TOTAL 1024
#define BM 128
#define BN 128
#define BK 64
#define KITERS (K_TOTAL / BK)
#define ROWB 128                       // bytes per smem row (64 fp16 = one swizzle row)
#define STAGE_BYTES (2 * 128 * ROWB)   // A 16KB + B 16KB
#define SMEM_TOTAL (2 * STAGE_BYTES)   // 64KB double-buffered

// -------- device scratch (allocation-free rule: __device__ globals) --------
__device__ __half g_xF[(size_t)M_TOTAL * K_TOTAL];
__device__ __half g_wF[(size_t)N_TOTAL * K_TOTAL];

// ---------------- helpers ----------------
__device__ __forceinline__ uint32_t smem_u32(const void* p) {
    uint32_t a;
    asm("{ .reg .u64 t; cvta.to.shared.u64 t, %1; cvt.u32.u64 %0, t; }" : "=r"(a) : "l"(p));
    return a;
}

#define CP_ASYNC16(dst, src) \
    asm volatile("cp.async.cg.shared.global [%0], [%1], 16;" :: "r"(dst), "l"(src) : "memory")
#define CP_COMMIT()  asm volatile("cp.async.commit_group;" ::: "memory")
#define CP_WAIT1()   asm volatile("cp.async.wait_group 1;" ::: "memory")
#define CP_WAIT0()   asm volatile("cp.async.wait_group 0;" ::: "memory")

#define LDMX4(R, addr)                                                          \
    asm volatile("ldmatrix.sync.aligned.m8n8.x4.shared.b16 {%0,%1,%2,%3}, [%4];"\
        : "=r"((R)[0]), "=r"((R)[1]), "=r"((R)[2]), "=r"((R)[3]) : "r"(addr))

#define MMA16816(ACC, A, B)                                                     \
    asm volatile("mma.sync.aligned.m16n8k16.row.col.f32.f16.f16.f32 "           \
        "{%0,%1,%2,%3}, {%4,%5,%6,%7}, {%8,%9}, {%0,%1,%2,%3};"                 \
        : "+f"((ACC)[0]), "+f"((ACC)[1]), "+f"((ACC)[2]), "+f"((ACC)[3])        \
        : "r"((A)[0]), "r"((A)[1]), "r"((A)[2]), "r"((A)[3]),                   \
          "r"((B)[0]), "r"((B)[1]))

// ---------------- Phase 1: transpose + fp16 convert ----------------
// src: [R][C] fp32 (per batch in z) -> dst: [C][R] fp16
__global__ void tsplit_kernel(const float* __restrict__ src,
                              __half* __restrict__ dst,
                              int R, int C)
{
    __shared__ float tile[32][33];
    int b = blockIdx.z;
    src += (size_t)b * R * C;
    dst += (size_t)b * R * C;
    int p0 = blockIdx.x * 32;
    int c0 = blockIdx.y * 32;
    int tx = threadIdx.x, ty = threadIdx.y;
    #pragma unroll
    for (int i = 0; i < 32; i += 8)
        tile[ty + i][tx] = src[(size_t)(c0 + ty + i) * C + p0 + tx];
    __syncthreads();
    #pragma unroll
    for (int i = 0; i < 32; i += 8) {
        float v = tile[tx][ty + i];
        dst[(size_t)(p0 + ty + i) * R + c0 + tx] = __float2half_rn(v);
    }
}

// ---------------- Phase 2: mma.sync fp16 GEMM ----------------
// SMEM stage: A = 128 rows x 128B, B = 128 rows x 128B.
// Row r, 16B chunk c (c=0..7 over BK=64 fp16) stored at ((c ^ (r&7))<<4):
// conflict-free for cp.async stores and all ldmatrix phases.

__global__ __launch_bounds__(512)
void gemm_mma_kernel(const float* __restrict__ bias, float* __restrict__ out)
{
    extern __shared__ char smem[];
    const uint32_t sbase = smem_u32(smem);

    const int tid  = threadIdx.x;
    const int lane = tid & 31;
    const int warp = tid >> 5;
    const int g    = lane >> 2;       // mma row within fragment
    const int tg   = lane & 3;        // mma col-pair selector
    const int wm   = warp & 3;        // 4 warps along M (32 rows each)
    const int wn   = warp >> 2;       // 4 warps along N (32 cols each)

    const int nb = blockIdx.x;        // 0..7   (N tile of 128)
    const int mb = blockIdx.y;        // 0..255 (M tile of 128)

    const __half* gA = g_xF + (size_t)mb * BM * K_TOTAL;
    const __half* gB = g_wF + (size_t)nb * BN * K_TOTAL;

    // ldmatrix per-lane addressing
    const int x7   = lane & 7;
    const int rA   = x7 + ((lane >> 3) & 1) * 8;          // row-in-16, A x4
    const int selA = lane >> 4;                           // k8 select, A x4
    const int rB   = ((lane >> 4) << 3) + x7;             // row-in-16, B x4 (nt pair)
    const int selB = (lane >> 3) & 1;                     // k8 select, B x4
    const uint32_t aBase = (uint32_t)(wm * 32 + rA) * ROWB;
    const uint32_t bBase = (uint32_t)(wn * 32 + rB) * ROWB;

    float acc[2][4][4];
    #pragma unroll
    for (int i = 0; i < 2; i++)
        #pragma unroll
        for (int j = 0; j < 4; j++)
            #pragma unroll
            for (int r = 0; r < 4; r++) acc[i][j][r] = 0.f;

    // ---- async staging of one k-stage (BK=64) into buffer buf ----
    auto stage_load = [&](int it, int buf) {
        const int k0 = it * BK;
        const uint32_t sA = sbase + buf * STAGE_BYTES;
        const uint32_t sB = sA + 128 * ROWB;
        #pragma unroll
        for (int i = 0; i < 2; i++) {                 // A: 1024 x 16B chunks
            int q = tid + i * 512;
            int r = q >> 3, c = q & 7;
            CP_ASYNC16(sA + (uint32_t)r * ROWB + (uint32_t)((c ^ (r & 7)) << 4),
                       gA + (size_t)r * K_TOTAL + k0 + c * 8);
        }
        #pragma unroll
        for (int i = 0; i < 2; i++) {                 // B: 1024 x 16B chunks
            int q = tid + i * 512;
            int r = q >> 3, c = q & 7;
            CP_ASYNC16(sB + (uint32_t)r * ROWB + (uint32_t)((c ^ (r & 7)) << 4),
                       gB + (size_t)r * K_TOTAL + k0 + c * 8);
        }
    };

    stage_load(0, 0);
    CP_COMMIT();

    for (int it = 0; it < KITERS; it++) {
        const int cur = it & 1;
        if (it + 1 < KITERS) {
            stage_load(it + 1, cur ^ 1);
            CP_COMMIT();
            CP_WAIT1();
        } else {
            CP_WAIT0();
        }
        __syncthreads();

        const uint32_t sA = sbase + cur * STAGE_BYTES;
        const uint32_t sB = sA + 128 * ROWB;

        #pragma unroll
        for (int kc = 0; kc < 4; kc++) {              // four k16 chunks in BK=64
            uint32_t a[8], b[8];
            #pragma unroll
            for (int mt = 0; mt < 2; mt++)
                LDMX4(a + mt * 4, sA + aBase + (uint32_t)mt * 16 * ROWB
                                  + (uint32_t)(((kc * 2 + selA) ^ x7) << 4));
            #pragma unroll
            for (int ntp = 0; ntp < 2; ntp++)         // each LDMX4 covers 2 nt
                LDMX4(b + ntp * 4, sB + bBase + (uint32_t)ntp * 16 * ROWB
                                   + (uint32_t)(((kc * 2 + selB) ^ x7) << 4));
            #pragma unroll
            for (int mt = 0; mt < 2; mt++)
                #pragma unroll
                for (int nt = 0; nt < 4; nt++)
                    MMA16816(acc[mt][nt], a + mt * 4, b + nt * 2);
        }
        __syncthreads();
    }

    // ---- epilogue: scatter to out[b][o][2h+i][2w+j], fused bias, float2 stores ----
    #pragma unroll
    for (int mt = 0; mt < 2; mt++) {
        int r0 = mb * 128 + wm * 32 + mt * 16 + g;
        #pragma unroll
        for (int half = 0; half < 2; half++) {
            int p  = r0 + half * 8;
            int bb = p >> 12;
            int h  = (p >> 6) & 63;
            int wp = p & 63;
            #pragma unroll
            for (int nt = 0; nt < 4; nt++) {
                int n  = nb * 128 + wn * 32 + nt * 8 + tg * 2;   // even -> (j=0, j=1)
                int o  = n >> 2;
                int ii = (n >> 1) & 1;
                float bo = __ldg(bias + o);
                size_t addr = (((size_t)(bb * 256 + o) * 128) + (h * 2 + ii)) * 128 + wp * 2;
                float2 v;
                v.x = acc[mt][nt][half * 2 + 0] + bo;
                v.y = acc[mt][nt][half * 2 + 1] + bo;
                *(float2*)(out + addr) = v;
            }
        }
    }
}

// ---------------- launch ----------------
extern "C" void kernel_launch(void* const* d_in, const int* in_sizes, int n_in,
                              void* d_out, int out_size)
{
    const float* x    = (const float*)d_in[0];   // [8,512,64,64]
    const float* wgt  = (const float*)d_in[1];   // [512,256,2,2] -> [512][1024]
    const float* bias = (const float*)d_in[2];   // [256]
    float* out = (float*)d_out;                  // [8,256,128,128]

    void *pxF, *pwF;
    cudaGetSymbolAddress(&pxF, g_xF);
    cudaGetSymbolAddress(&pwF, g_wF);

    // Phase 1: x [512][4096] per batch -> [4096][512]; w [512][1024] -> [1024][512]
    tsplit_kernel<<<dim3(4096 / 32, 512 / 32, 8), dim3(32, 8)>>>(
        x, (__half*)pxF, 512, 4096);
    tsplit_kernel<<<dim3(1024 / 32, 512 / 32, 1), dim3(32, 8)>>>(
        wgt, (__half*)pwF, 512, 1024);

    // Phase 2
    static int attr_set = 0;
    if (!attr_set) {
        cudaFuncSetAttribute(gemm_mma_kernel,
                             cudaFuncAttributeMaxDynamicSharedMemorySize, SMEM_TOTAL);
        attr_set = 1;
    }
    dim3 grid(N_TOTAL / BN, M_TOTAL / BM);   // (8, 256) — nb fastest for A-tile L2 reuse
    gemm_mma_kernel<<<grid, 512, SMEM_TOTAL>>>(bias, out);
}

// round 7
// speedup vs baseline: 5.1731x; 1.2546x over previous
#include <cuda_runtime.h>
#include <cuda_fp16.h>
#include <cstdint>

// ConvTranspose2d (k==s==2) == GEMM: M=32768 pixels, N=1024 (o*4+i*2+j), K=512 (c)
// Single-pass fp16 mma (fp32 accumulate): rel_err ~2.8e-4 < 1e-3 gate (measured R6).
// Phase 1: transpose+convert  x -> g_xF [32768][512] fp16,  w -> g_wF [1024][512] fp16
// Phase 2: mma.sync fp16 GEMM. 256 threads / 8 warps (4Mx2N), warp tile 32x64,
//          2 CTAs/SM, BK=64 double-buffered cp.async, all-LDMX4 loads, fused epilogue.

#define M_TOTAL 32768
#define K_TOTAL 512
#define N_TOTAL 1024
#define BM 128
#define BN 128
#define BK 64
#define KITERS (K_TOTAL / BK)
#define ROWB 128                       // bytes per smem row (64 fp16)
#define STAGE_BYTES (2 * 128 * ROWB)   // A 16KB + B 16KB
#define SMEM_TOTAL (2 * STAGE_BYTES)   // 64KB double-buffered -> 2 CTAs/SM

// -------- device scratch (allocation-free rule: __device__ globals) --------
__device__ __half g_xF[(size_t)M_TOTAL * K_TOTAL];
__device__ __half g_wF[(size_t)N_TOTAL * K_TOTAL];

// ---------------- helpers ----------------
__device__ __forceinline__ uint32_t smem_u32(const void* p) {
    uint32_t a;
    asm("{ .reg .u64 t; cvta.to.shared.u64 t, %1; cvt.u32.u64 %0, t; }" : "=r"(a) : "l"(p));
    return a;
}

#define CP_ASYNC16(dst, src) \
    asm volatile("cp.async.cg.shared.global [%0], [%1], 16;" :: "r"(dst), "l"(src) : "memory")
#define CP_COMMIT()  asm volatile("cp.async.commit_group;" ::: "memory")
#define CP_WAIT1()   asm volatile("cp.async.wait_group 1;" ::: "memory")
#define CP_WAIT0()   asm volatile("cp.async.wait_group 0;" ::: "memory")

#define LDMX4(R, addr)                                                          \
    asm volatile("ldmatrix.sync.aligned.m8n8.x4.shared.b16 {%0,%1,%2,%3}, [%4];"\
        : "=r"((R)[0]), "=r"((R)[1]), "=r"((R)[2]), "=r"((R)[3]) : "r"(addr))

#define MMA16816(ACC, A, B)                                                     \
    asm volatile("mma.sync.aligned.m16n8k16.row.col.f32.f16.f16.f32 "           \
        "{%0,%1,%2,%3}, {%4,%5,%6,%7}, {%8,%9}, {%0,%1,%2,%3};"                 \
        : "+f"((ACC)[0]), "+f"((ACC)[1]), "+f"((ACC)[2]), "+f"((ACC)[3])        \
        : "r"((A)[0]), "r"((A)[1]), "r"((A)[2]), "r"((A)[3]),                   \
          "r"((B)[0]), "r"((B)[1]))

// ---------------- Phase 1: transpose + fp16 convert ----------------
// src: [R][C] fp32 (per batch in z) -> dst: [C][R] fp16
__global__ void tsplit_kernel(const float* __restrict__ src,
                              __half* __restrict__ dst,
                              int R, int C)
{
    __shared__ float tile[32][33];
    int b = blockIdx.z;
    src += (size_t)b * R * C;
    dst += (size_t)b * R * C;
    int p0 = blockIdx.x * 32;
    int c0 = blockIdx.y * 32;
    int tx = threadIdx.x, ty = threadIdx.y;
    #pragma unroll
    for (int i = 0; i < 32; i += 8)
        tile[ty + i][tx] = src[(size_t)(c0 + ty + i) * C + p0 + tx];
    __syncthreads();
    #pragma unroll
    for (int i = 0; i < 32; i += 8) {
        float v = tile[tx][ty + i];
        dst[(size_t)(p0 + ty + i) * R + c0 + tx] = __float2half_rn(v);
    }
}

// ---------------- Phase 2: mma.sync fp16 GEMM ----------------
// SMEM stage: A = 128 rows x 128B, B = 128 rows x 128B.
// Row r, 16B chunk c stored at ((c ^ (r&7))<<4): conflict-free for cp.async
// stores and all ldmatrix phases.

__global__ __launch_bounds__(256, 2)
void gemm_mma_kernel(const float* __restrict__ bias, float* __restrict__ out)
{
    extern __shared__ char smem[];
    const uint32_t sbase = smem_u32(smem);

    const int tid  = threadIdx.x;
    const int lane = tid & 31;
    const int warp = tid >> 5;
    const int g    = lane >> 2;       // mma row within fragment
    const int tg   = lane & 3;        // mma col-pair selector
    const int wm   = warp & 3;        // 4 warps along M (32 rows each)
    const int wn   = warp >> 2;       // 2 warps along N (64 cols each)

    const int nb = blockIdx.x;        // 0..7   (N tile of 128)
    const int mb = blockIdx.y;        // 0..255 (M tile of 128)

    const __half* gA = g_xF + (size_t)mb * BM * K_TOTAL;
    const __half* gB = g_wF + (size_t)nb * BN * K_TOTAL;

    // ldmatrix per-lane addressing
    const int x7   = lane & 7;
    const int rA   = x7 + ((lane >> 3) & 1) * 8;          // row-in-16, A x4
    const int selA = lane >> 4;                           // k8 select, A x4
    const int rB   = ((lane >> 4) << 3) + x7;             // row-in-16, B x4 (nt pair)
    const int selB = (lane >> 3) & 1;                     // k8 select, B x4
    const uint32_t aBase = (uint32_t)(wm * 32 + rA) * ROWB;
    const uint32_t bBase = (uint32_t)(wn * 64 + rB) * ROWB;

    float acc[2][8][4];
    #pragma unroll
    for (int i = 0; i < 2; i++)
        #pragma unroll
        for (int j = 0; j < 8; j++)
            #pragma unroll
            for (int r = 0; r < 4; r++) acc[i][j][r] = 0.f;

    // ---- async staging of one k-stage (BK=64) into buffer buf ----
    auto stage_load = [&](int it, int buf) {
        const int k0 = it * BK;
        const uint32_t sA = sbase + buf * STAGE_BYTES;
        const uint32_t sB = sA + 128 * ROWB;
        #pragma unroll
        for (int i = 0; i < 4; i++) {                 // A: 1024 x 16B chunks
            int q = tid + i * 256;
            int r = q >> 3, c = q & 7;
            CP_ASYNC16(sA + (uint32_t)r * ROWB + (uint32_t)((c ^ (r & 7)) << 4),
                       gA + (size_t)r * K_TOTAL + k0 + c * 8);
        }
        #pragma unroll
        for (int i = 0; i < 4; i++) {                 // B: 1024 x 16B chunks
            int q = tid + i * 256;
            int r = q >> 3, c = q & 7;
            CP_ASYNC16(sB + (uint32_t)r * ROWB + (uint32_t)((c ^ (r & 7)) << 4),
                       gB + (size_t)r * K_TOTAL + k0 + c * 8);
        }
    };

    stage_load(0, 0);
    CP_COMMIT();

    for (int it = 0; it < KITERS; it++) {
        const int cur = it & 1;
        if (it + 1 < KITERS) {
            stage_load(it + 1, cur ^ 1);
            CP_COMMIT();
            CP_WAIT1();
        } else {
            CP_WAIT0();
        }
        __syncthreads();

        const uint32_t sA = sbase + cur * STAGE_BYTES;
        const uint32_t sB = sA + 128 * ROWB;

        #pragma unroll
        for (int kc = 0; kc < 4; kc++) {              // four k16 chunks in BK=64
            uint32_t a[8], b[16];
            #pragma unroll
            for (int mt = 0; mt < 2; mt++)
                LDMX4(a + mt * 4, sA + aBase + (uint32_t)mt * 16 * ROWB
                                  + (uint32_t)(((kc * 2 + selA) ^ x7) << 4));
            #pragma unroll
            for (int ntp = 0; ntp < 4; ntp++)         // each LDMX4 covers 2 nt
                LDMX4(b + ntp * 4, sB + bBase + (uint32_t)ntp * 16 * ROWB
                                   + (uint32_t)(((kc * 2 + selB) ^ x7) << 4));
            #pragma unroll
            for (int mt = 0; mt < 2; mt++)
                #pragma unroll
                for (int nt = 0; nt < 8; nt++)
                    MMA16816(acc[mt][nt], a + mt * 4, b + nt * 2);
        }
        __syncthreads();
    }

    // ---- epilogue: scatter to out[b][o][2h+i][2w+j], fused bias, float2 stores ----
    #pragma unroll
    for (int mt = 0; mt < 2; mt++) {
        int r0 = mb * 128 + wm * 32 + mt * 16 + g;
        #pragma unroll
        for (int half = 0; half < 2; half++) {
            int p  = r0 + half * 8;
            int bb = p >> 12;
            int h  = (p >> 6) & 63;
            int wp = p & 63;
            #pragma unroll
            for (int nt = 0; nt < 8; nt++) {
                int n  = nb * 128 + wn * 64 + nt * 8 + tg * 2;   // even -> (j=0, j=1)
                int o  = n >> 2;
                int ii = (n >> 1) & 1;
                float bo = __ldg(bias + o);
                size_t addr = (((size_t)(bb * 256 + o) * 128) + (h * 2 + ii)) * 128 + wp * 2;
                float2 v;
                v.x = acc[mt][nt][half * 2 + 0] + bo;
                v.y = acc[mt][nt][half * 2 + 1] + bo;
                *(float2*)(out + addr) = v;
            }
        }
    }
}

// ---------------- launch ----------------
extern "C" void kernel_launch(void* const* d_in, const int* in_sizes, int n_in,
                              void* d_out, int out_size)
{
    const float* x    = (const float*)d_in[0];   // [8,512,64,64]
    const float* wgt  = (const float*)d_in[1];   // [512,256,2,2] -> [512][1024]
    const float* bias = (const float*)d_in[2];   // [256]
    float* out = (float*)d_out;                  // [8,256,128,128]

    void *pxF, *pwF;
    cudaGetSymbolAddress(&pxF, g_xF);
    cudaGetSymbolAddress(&pwF, g_wF);

    // Phase 1: x [512][4096] per batch -> [4096][512]; w [512][1024] -> [1024][512]
    tsplit_kernel<<<dim3(4096 / 32, 512 / 32, 8), dim3(32, 8)>>>(
        x, (__half*)pxF, 512, 4096);
    tsplit_kernel<<<dim3(1024 / 32, 512 / 32, 1), dim3(32, 8)>>>(
        wgt, (__half*)pwF, 512, 1024);

    // Phase 2
    static int attr_set = 0;
    if (!attr_set) {
        cudaFuncSetAttribute(gemm_mma_kernel,
                             cudaFuncAttributeMaxDynamicSharedMemorySize, SMEM_TOTAL);
        attr_set = 1;
    }
    dim3 grid(N_TOTAL / BN, M_TOTAL / BM);   // (8, 256) — nb fastest for A-tile L2 reuse
    gemm_mma_kernel<<<grid, 256, SMEM_TOTAL>>>(bias, out);
}

// round 8
// speedup vs baseline: 5.3674x; 1.0375x over previous
#include <cuda_runtime.h>
#include <cuda_fp16.h>
#include <cstdint>

// ConvTranspose2d (k==s==2) == GEMM: M=32768 pixels, N=1024 (o*4+i*2+j), K=512 (c)
// Single-pass fp16 mma (fp32 accumulate): rel_err ~2.8e-4 < 1e-3 gate (measured).
// Phase 1: transpose+convert  x -> g_xF [32768][512] fp16,  w -> g_wF [1024][512] fp16
//          (64c x 32p tiles, half2 stores -> 128B store transactions)
// Phase 2: mma.sync fp16 GEMM. 256 threads / 8 warps (4Mx2N), warp tile 32x64,
//          2 CTAs/SM, BK=64, THREE-stage cp.async pipeline with ONE sync per k-iter,
//          all-LDMX4 fragment loads, fused bias + pixel-shuffle epilogue.

#define M_TOTAL 32768
#define K_TOTAL 512
#define N_TOTAL 1024
#define BM 128
#define BN 128
#define BK 64
#define KITERS (K_TOTAL / BK)
#define ROWB 128                       // bytes per smem row (64 fp16)
#define STAGE_BYTES (2 * 128 * ROWB)   // A 16KB + B 16KB
#define NSTAGE 3
#define SMEM_TOTAL (NSTAGE * STAGE_BYTES)   // 96KB -> 2 CTAs/SM (192KB < 228KB)

// -------- device scratch (allocation-free rule: __device__ globals) --------
__device__ __half g_xF[(size_t)M_TOTAL * K_TOTAL];
__device__ __half g_wF[(size_t)N_TOTAL * K_TOTAL];

// ---------------- helpers ----------------
__device__ __forceinline__ uint32_t smem_u32(const void* p) {
    uint32_t a;
    asm("{ .reg .u64 t; cvta.to.shared.u64 t, %1; cvt.u32.u64 %0, t; }" : "=r"(a) : "l"(p));
    return a;
}

#define CP_ASYNC16(dst, src) \
    asm volatile("cp.async.cg.shared.global [%0], [%1], 16;" :: "r"(dst), "l"(src) : "memory")
#define CP_COMMIT()  asm volatile("cp.async.commit_group;" ::: "memory")
#define CP_WAIT1()   asm volatile("cp.async.wait_group 1;" ::: "memory")
#define CP_WAIT0()   asm volatile("cp.async.wait_group 0;" ::: "memory")

#define LDMX4(R, addr)                                                          \
    asm volatile("ldmatrix.sync.aligned.m8n8.x4.shared.b16 {%0,%1,%2,%3}, [%4];"\
        : "=r"((R)[0]), "=r"((R)[1]), "=r"((R)[2]), "=r"((R)[3]) : "r"(addr))

#define MMA16816(ACC, A, B)                                                     \
    asm volatile("mma.sync.aligned.m16n8k16.row.col.f32.f16.f16.f32 "           \
        "{%0,%1,%2,%3}, {%4,%5,%6,%7}, {%8,%9}, {%0,%1,%2,%3};"                 \
        : "+f"((ACC)[0]), "+f"((ACC)[1]), "+f"((ACC)[2]), "+f"((ACC)[3])        \
        : "r"((A)[0]), "r"((A)[1]), "r"((A)[2]), "r"((A)[3]),                   \
          "r"((B)[0]), "r"((B)[1]))

// ---------------- Phase 1: transpose + fp16 convert ----------------
// src: [R][C] fp32 (per batch in z) -> dst: [C][R] fp16.
// 64 c-rows x 32 p-cols per block; writes are half2 (128B per warp).
__global__ void tsplit_kernel(const float* __restrict__ src,
                              __half* __restrict__ dst,
                              int R, int C)
{
    __shared__ float tile[64][33];
    int b = blockIdx.z;
    src += (size_t)b * R * C;
    dst += (size_t)b * R * C;
    int p0 = blockIdx.x * 32;
    int c0 = blockIdx.y * 64;
    int tx = threadIdx.x, ty = threadIdx.y;
    #pragma unroll
    for (int i = 0; i < 64; i += 8)
        tile[ty + i][tx] = src[(size_t)(c0 + ty + i) * C + p0 + tx];
    __syncthreads();
    #pragma unroll
    for (int j = 0; j < 32; j += 8) {
        int p = ty + j;
        __half2 v = __floats2half2_rn(tile[tx * 2][p], tile[tx * 2 + 1][p]);
        *(__half2*)(dst + (size_t)(p0 + p) * R + c0 + tx * 2) = v;
    }
}

// ---------------- Phase 2: mma.sync fp16 GEMM ----------------
// SMEM stage: A = 128 rows x 128B, B = 128 rows x 128B.
// Row r, 16B chunk c stored at ((c ^ (r&7))<<4): conflict-free for cp.async
// stores and all ldmatrix phases.

__global__ __launch_bounds__(256, 2)
void gemm_mma_kernel(const float* __restrict__ bias, float* __restrict__ out)
{
    extern __shared__ char smem[];
    const uint32_t sbase = smem_u32(smem);

    const int tid  = threadIdx.x;
    const int lane = tid & 31;
    const int warp = tid >> 5;
    const int g    = lane >> 2;       // mma row within fragment
    const int tg   = lane & 3;        // mma col-pair selector
    const int wm   = warp & 3;        // 4 warps along M (32 rows each)
    const int wn   = warp >> 2;       // 2 warps along N (64 cols each)

    const int nb = blockIdx.x;        // 0..7   (N tile of 128)
    const int mb = blockIdx.y;        // 0..255 (M tile of 128)

    const __half* gA = g_xF + (size_t)mb * BM * K_TOTAL;
    const __half* gB = g_wF + (size_t)nb * BN * K_TOTAL;

    // ldmatrix per-lane addressing
    const int x7   = lane & 7;
    const int rA   = x7 + ((lane >> 3) & 1) * 8;          // row-in-16, A x4
    const int selA = lane >> 4;                           // k8 select, A x4
    const int rB   = ((lane >> 4) << 3) + x7;             // row-in-16, B x4 (nt pair)
    const int selB = (lane >> 3) & 1;                     // k8 select, B x4
    const uint32_t aBase = (uint32_t)(wm * 32 + rA) * ROWB;
    const uint32_t bBase = (uint32_t)(wn * 64 + rB) * ROWB;

    float acc[2][8][4];
    #pragma unroll
    for (int i = 0; i < 2; i++)
        #pragma unroll
        for (int j = 0; j < 8; j++)
            #pragma unroll
            for (int r = 0; r < 4; r++) acc[i][j][r] = 0.f;

    // ---- async staging of one k-stage (BK=64) into stage buffer ----
    auto stage_load = [&](int it, int buf) {
        const int k0 = it * BK;
        const uint32_t sA = sbase + buf * STAGE_BYTES;
        const uint32_t sB = sA + 128 * ROWB;
        #pragma unroll
        for (int i = 0; i < 4; i++) {                 // A: 1024 x 16B chunks
            int q = tid + i * 256;
            int r = q >> 3, c = q & 7;
            CP_ASYNC16(sA + (uint32_t)r * ROWB + (uint32_t)((c ^ (r & 7)) << 4),
                       gA + (size_t)r * K_TOTAL + k0 + c * 8);
        }
        #pragma unroll
        for (int i = 0; i < 4; i++) {                 // B: 1024 x 16B chunks
            int q = tid + i * 256;
            int r = q >> 3, c = q & 7;
            CP_ASYNC16(sB + (uint32_t)r * ROWB + (uint32_t)((c ^ (r & 7)) << 4),
                       gB + (size_t)r * K_TOTAL + k0 + c * 8);
        }
    };

    // prologue: two stages in flight
    stage_load(0, 0);
    CP_COMMIT();
    stage_load(1, 1);
    CP_COMMIT();

    for (int it = 0; it < KITERS; it++) {
        // wait for stage `it` (leave one newer group pending), except last iter
        if (it + 1 < KITERS) { CP_WAIT1(); } else { CP_WAIT0(); }
        // single barrier: releases compute(it) AND certifies buffer (it+2)%3
        // (== (it-1)%3, consumed by all threads before this barrier) for refill
        __syncthreads();
        if (it + 2 < KITERS) {
            stage_load(it + 2, (it + 2) % NSTAGE);
            CP_COMMIT();
        }

        const uint32_t sA = sbase + (it % NSTAGE) * STAGE_BYTES;
        const uint32_t sB = sA + 128 * ROWB;

        #pragma unroll
        for (int kc = 0; kc < 4; kc++) {              // four k16 chunks in BK=64
            uint32_t a[8], b[16];
            #pragma unroll
            for (int mt = 0; mt < 2; mt++)
                LDMX4(a + mt * 4, sA + aBase + (uint32_t)mt * 16 * ROWB
                                  + (uint32_t)(((kc * 2 + selA) ^ x7) << 4));
            #pragma unroll
            for (int ntp = 0; ntp < 4; ntp++)         // each LDMX4 covers 2 nt
                LDMX4(b + ntp * 4, sB + bBase + (uint32_t)ntp * 16 * ROWB
                                   + (uint32_t)(((kc * 2 + selB) ^ x7) << 4));
            #pragma unroll
            for (int mt = 0; mt < 2; mt++)
                #pragma unroll
                for (int nt = 0; nt < 8; nt++)
                    MMA16816(acc[mt][nt], a + mt * 4, b + nt * 2);
        }
    }

    // ---- epilogue: scatter to out[b][o][2h+i][2w+j], fused bias, float2 stores ----
    #pragma unroll
    for (int mt = 0; mt < 2; mt++) {
        int r0 = mb * 128 + wm * 32 + mt * 16 + g;
        #pragma unroll
        for (int half = 0; half < 2; half++) {
            int p  = r0 + half * 8;
            int bb = p >> 12;
            int h  = (p >> 6) & 63;
            int wp = p & 63;
            #pragma unroll
            for (int nt = 0; nt < 8; nt++) {
                int n  = nb * 128 + wn * 64 + nt * 8 + tg * 2;   // even -> (j=0, j=1)
                int o  = n >> 2;
                int ii = (n >> 1) & 1;
                float bo = __ldg(bias + o);
                size_t addr = (((size_t)(bb * 256 + o) * 128) + (h * 2 + ii)) * 128 + wp * 2;
                float2 v;
                v.x = acc[mt][nt][half * 2 + 0] + bo;
                v.y = acc[mt][nt][half * 2 + 1] + bo;
                *(float2*)(out + addr) = v;
            }
        }
    }
}

// ---------------- launch ----------------
extern "C" void kernel_launch(void* const* d_in, const int* in_sizes, int n_in,
                              void* d_out, int out_size)
{
    const float* x    = (const float*)d_in[0];   // [8,512,64,64]
    const float* wgt  = (const float*)d_in[1];   // [512,256,2,2] -> [512][1024]
    const float* bias = (const float*)d_in[2];   // [256]
    float* out = (float*)d_out;                  // [8,256,128,128]

    void *pxF, *pwF;
    cudaGetSymbolAddress(&pxF, g_xF);
    cudaGetSymbolAddress(&pwF, g_wF);

    // Phase 1: x [512][4096] per batch -> [4096][512]; w [512][1024] -> [1024][512]
    tsplit_kernel<<<dim3(4096 / 32, 512 / 64, 8), dim3(32, 8)>>>(
        x, (__half*)pxF, 512, 4096);
    tsplit_kernel<<<dim3(1024 / 32, 512 / 64, 1), dim3(32, 8)>>>(
        wgt, (__half*)pwF, 512, 1024);

    // Phase 2
    static int attr_set = 0;
    if (!attr_set) {
        cudaFuncSetAttribute(gemm_mma_kernel,
                             cudaFuncAttributeMaxDynamicSharedMemorySize, SMEM_TOTAL);
        attr_set = 1;
    }
    dim3 grid(N_TOTAL / BN, M_TOTAL / BM);   // (8, 256) — nb fastest for A-tile L2 reuse
    gemm_mma_kernel<<<grid, 256, SMEM_TOTAL>>>(bias, out);
}